// round 15
// baseline (speedup 1.0000x reference)
#include <cuda_runtime.h>
#include <cuda_fp16.h>
#include <cstdint>
#include <math.h>

// ---------------- problem constants ----------------
#define T_TOK 4096
#define D_DIM 2048
#define H_DIM 688
#define HP2   704          // g_h pitch (pad cols exact zeros)
#define E_NUM 8
#define CAP   1536
#define NROWS (E_NUM * CAP)   // 12288

// GEMM tiling: CTA 256x128, 256 threads, 8 warps of 64x64, fp16 mma m16n8k16, BK=32
#define CTA_M 256
#define CTA_N 128
#define BK 32                  // k-depth per stage = two mma-k
#define BKPH 40                // A smem pitch (halfs) = 20 u32: (g*20+t)%32 bijective
#define BNPH 136               // B smem pitch (halfs); 272B rows -> ldmatrix conflict-free
#define A_ST (CTA_M * BKPH * 2)   // 20480
#define B_ST (BK * BNPH * 2)      // 8704
#define ST_BYTES (A_ST + B_ST)    // 29184
#define STAGES 6
#define PRELOAD 5                 // stages in flight; wait_group 4
#define GEMM_SMEM (1024 + STAGES * ST_BYTES)   // 176128

// ---------------- device scratch (static, no runtime allocs) ----------------
__device__ __align__(256) __half g_Wgh[(size_t)E_NUM * D_DIM * H_DIM];
__device__ __align__(256) __half g_Wuh[(size_t)E_NUM * D_DIM * H_DIM];
__device__ __align__(256) __half g_Wdh[(size_t)E_NUM * H_DIM * D_DIM];
__device__ __align__(256) __half g_xh [(size_t)T_TOK * D_DIM];
__device__ __align__(256) __half g_hh [(size_t)NROWS * HP2];
__device__ float g_yb [(size_t)NROWS * D_DIM];
__device__ int   g_row_token[NROWS];
__device__ int   g_tok_slot[T_TOK * 2];
__device__ int   g_counts[E_NUM];

// ---------------- helpers ----------------
__device__ __forceinline__ uint32_t smem_u32(const void* p) {
    uint32_t a;
    asm("{ .reg .u64 t; cvta.to.shared.u64 t, %1; cvt.u32.u64 %0, t; }" : "=r"(a) : "l"(p));
    return a;
}
__device__ __forceinline__ void cp_async16(uint32_t dst, const void* src, uint32_t sz) {
    asm volatile("cp.async.cg.shared.global [%0], [%1], 16, %2;" :: "r"(dst), "l"(src), "r"(sz) : "memory");
}
__device__ __forceinline__ void cp_commit() {
    asm volatile("cp.async.commit_group;" ::: "memory");
}
__device__ __forceinline__ void cp_wait4() {
    asm volatile("cp.async.wait_group 4;" ::: "memory");
}
// fp16 m16n8k16 row.col, fp32 accum: D += A*B
__device__ __forceinline__ void mma_f16(float* c, const uint32_t* a, const uint32_t* b) {
    asm volatile(
        "mma.sync.aligned.m16n8k16.row.col.f32.f16.f16.f32 "
        "{%0,%1,%2,%3}, {%4,%5,%6,%7}, {%8,%9}, {%0,%1,%2,%3};"
        : "+f"(c[0]), "+f"(c[1]), "+f"(c[2]), "+f"(c[3])
        : "r"(a[0]), "r"(a[1]), "r"(a[2]), "r"(a[3]), "r"(b[0]), "r"(b[1]));
}
__device__ __forceinline__ void ldsm_x4_trans(uint32_t& r0, uint32_t& r1, uint32_t& r2, uint32_t& r3,
                                              uint32_t addr) {
    asm volatile("ldmatrix.sync.aligned.m8n8.x4.trans.shared.b16 {%0,%1,%2,%3}, [%4];"
        : "=r"(r0), "=r"(r1), "=r"(r2), "=r"(r3) : "r"(addr));
}

// ================= prep: fp32 -> fp16 RN copies (MLP=2) =================
__global__ void f2h_kernel(const float4* __restrict__ src, uint2* __restrict__ dst, int half_n) {
    int i = blockIdx.x * 256 + threadIdx.x;
    float4 v0 = src[i];
    float4 v1 = src[i + half_n];
    __half2 a0 = __floats2half2_rn(v0.x, v0.y);
    __half2 b0 = __floats2half2_rn(v0.z, v0.w);
    __half2 a1 = __floats2half2_rn(v1.x, v1.y);
    __half2 b1 = __floats2half2_rn(v1.z, v1.w);
    uint2 o0, o1;
    o0.x = *reinterpret_cast<uint32_t*>(&a0);
    o0.y = *reinterpret_cast<uint32_t*>(&b0);
    o1.x = *reinterpret_cast<uint32_t*>(&a1);
    o1.y = *reinterpret_cast<uint32_t*>(&b1);
    dst[i] = o0;
    dst[i + half_n] = o1;
}

// ================= dispatch =================
__global__ void zero_counts_kernel() {
    if (threadIdx.x < E_NUM) g_counts[threadIdx.x] = 0;
}
__global__ void dispatch_kernel(const int* __restrict__ topk_idx) {
    int i = blockIdx.x * 256 + threadIdx.x;
    if (i >= T_TOK * 2) return;
    int e = topk_idx[i];
    int pos = atomicAdd(&g_counts[e], 1);
    if (pos < CAP) {
        int slot = e * CAP + pos;
        g_row_token[slot] = i >> 1;
        g_tok_slot[i] = slot;
    } else {
        g_tok_slot[i] = -1;
    }
}

// ================= GEMM inner stage (fp16, BK=32: two mma-k) =================
// 8 warps: wm=(w&3)*64, wn=(w>>2)*64; warp tile 64x64, acc[4][8][4].
__device__ __forceinline__ void gemm_stage(
    const uint32_t* __restrict__ Asu, uint32_t baddr,
    int wm, int g, int t, float acc[4][8][4])
{
    #pragma unroll
    for (int ks = 0; ks < 2; ks++) {
        uint32_t af[4][4];
        #pragma unroll
        for (int mi = 0; mi < 4; mi++) {
            int rb = (wm + mi * 16 + g) * (BKPH / 2) + ks * 8 + t;   // u32 units: 20/row
            af[mi][0] = Asu[rb];
            af[mi][1] = Asu[rb + 8 * (BKPH / 2)];
            af[mi][2] = Asu[rb + 4];
            af[mi][3] = Asu[rb + 8 * (BKPH / 2) + 4];
        }
        uint32_t bf[8][2];
        uint32_t bks = baddr + ks * (16 * BNPH * 2);
        #pragma unroll
        for (int q = 0; q < 4; q++)
            ldsm_x4_trans(bf[2 * q][0], bf[2 * q][1], bf[2 * q + 1][0], bf[2 * q + 1][1],
                          bks + q * 32);
        #pragma unroll
        for (int mi = 0; mi < 4; mi++)
            #pragma unroll
            for (int j = 0; j < 8; j++)
                mma_f16(acc[mi][j], af[mi], bf[j]);
    }
}

// ================= GEMM1: h = silu(x*Wg) * (x*Wu) =================
// grid (11, 6, 8) = (64-h tile, 256-m tile, expert), 256 threads.
__global__ void __launch_bounds__(256, 1) gemm1_kernel() {
    extern __shared__ char smem[];
    const int e = blockIdx.z, mt = blockIdx.y;
    int count = g_counts[e]; if (count > CAP) count = CAP;
    const int m0 = mt * CTA_M;
    if (m0 >= count) return;
    const int h0 = blockIdx.x * 64;
    const uint32_t sb = smem_u32(smem);
    const int tid = threadIdx.x, w = tid >> 5, lid = tid & 31;
    const int wm = (w & 3) * 64, wn = (w >> 2) * 64;
    const int g = lid >> 2, t = lid & 3;
    int* tok_sm = (int*)smem;

    {
        int m = m0 + tid;
        tok_sm[tid] = (m < count) ? g_row_token[e * CAP + m] : -1;
    }
    __syncthreads();

    // B chunk geometry: 2 chunks/thread over 512 chunks of [32][128]
    const __half* wsrc[2];
    uint32_t bsz_[2]; int kk_[2]; int bn_[2];
    #pragma unroll
    for (int i = 0; i < 2; i++) {
        int chunk = i * 256 + tid;
        int kk = chunk >> 4;            // 0..31
        int c  = chunk & 15;
        int sel = c & 1;
        int hrel = 8 * (c >> 1);
        int h_glob = h0 + hrel;
        bsz_[i] = (h_glob < H_DIM) ? 16u : 0u;
        int h_src = (h_glob < H_DIM) ? h_glob : 0;
        wsrc[i] = (sel ? g_Wuh : g_Wgh) + ((size_t)e * D_DIM + kk) * H_DIM + h_src;
        kk_[i] = kk; bn_[i] = 8 * c;
    }

    const uint32_t boff = (((uint32_t)(lid & 15)) * BNPH + ((lid >> 4) & 1) * 8) * 2 + wn * 2;

    auto load_stage = [&](int s, int kc) {
        const int k0 = kc * BK;
        uint32_t abase = sb + 1024 + s * ST_BYTES;
        uint32_t bbase = abase + A_ST;
        #pragma unroll
        for (int i = 0; i < 4; i++) {
            int idx = i * 256 + tid; int r = idx >> 2, c4 = idx & 3;
            int tok = tok_sm[r];
            const __half* src = (tok >= 0) ? (g_xh + (size_t)tok * D_DIM + k0 + 8 * c4) : g_xh;
            cp_async16(abase + r * (BKPH * 2) + c4 * 16, src, (tok >= 0) ? 16u : 0u);
        }
        #pragma unroll
        for (int i = 0; i < 2; i++)
            cp_async16(bbase + (kk_[i] * BNPH + bn_[i]) * 2,
                       wsrc[i] + (size_t)k0 * H_DIM, bsz_[i]);
    };

    float acc[4][8][4];
    #pragma unroll
    for (int mi = 0; mi < 4; mi++)
        #pragma unroll
        for (int j = 0; j < 8; j++)
            #pragma unroll
            for (int cc = 0; cc < 4; cc++) acc[mi][j][cc] = 0.f;

    const int NK = D_DIM / BK;   // 64
    for (int s = 0; s < PRELOAD; s++) {
        if (s < NK) load_stage(s, s);
        cp_commit();
    }

    #pragma unroll 1
    for (int kc = 0; kc < NK; kc++) {
        cp_wait4();
        __syncthreads();
        if (kc + PRELOAD < NK) load_stage((kc + PRELOAD) % STAGES, kc + PRELOAD);
        cp_commit();
        const uint32_t* Asu = (const uint32_t*)(smem + 1024 + (kc % STAGES) * ST_BYTES);
        uint32_t baddr = sb + 1024 + (kc % STAGES) * ST_BYTES + A_ST + boff;
        gemm_stage(Asu, baddr, wm, g, t, acc);
    }

    // epilogue: silu(gate)*up -> g_hh (fp16). ntile pairs (2p, 2p+1); h = h0 + wn/2 + 8p + 2t.
    #pragma unroll
    for (int mi = 0; mi < 4; mi++) {
        size_t r = (size_t)(e * CAP + m0 + wm + mi * 16 + g);
        #pragma unroll
        for (int p = 0; p < 4; p++) {
            float* ga = acc[mi][2 * p];
            float* ua = acc[mi][2 * p + 1];
            int hc = h0 + (wn >> 1) + 8 * p + 2 * t;
            float h00 = ga[0] / (1.f + __expf(-ga[0])) * ua[0];
            float h01 = ga[1] / (1.f + __expf(-ga[1])) * ua[1];
            float h10 = ga[2] / (1.f + __expf(-ga[2])) * ua[2];
            float h11 = ga[3] / (1.f + __expf(-ga[3])) * ua[3];
            *(__half2*)(g_hh + r * HP2 + hc)       = __floats2half2_rn(h00, h01);
            *(__half2*)(g_hh + (r + 8) * HP2 + hc) = __floats2half2_rn(h10, h11);
        }
    }
}

// ================= GEMM2: yb = h * W_down (K=688, 22 stages, tail zero-filled) =================
// grid (16, 6, 8) = (128-d tile, 256-m tile, expert), 256 threads.
__global__ void __launch_bounds__(256, 1) gemm2_kernel() {
    extern __shared__ char smem[];
    const int e = blockIdx.z, mt = blockIdx.y;
    int count = g_counts[e]; if (count > CAP) count = CAP;
    const int m0 = mt * CTA_M;
    if (m0 >= count) return;
    const int d0 = blockIdx.x * CTA_N;
    const uint32_t sb = smem_u32(smem);
    const int tid = threadIdx.x, w = tid >> 5, lid = tid & 31;
    const int wm = (w & 3) * 64, wn = (w >> 2) * 64;
    const int g = lid >> 2, t = lid & 3;

    const __half* Ab = g_hh + (size_t)(e * CAP + m0) * HP2;
    const __half* bptr[2]; int kk_[2]; int cc_[2];
    #pragma unroll
    for (int i = 0; i < 2; i++) {
        int chunk = i * 256 + tid;
        int kk = chunk >> 4, c = chunk & 15;
        bptr[i] = g_Wdh + ((size_t)e * H_DIM + kk) * D_DIM + d0 + 8 * c;
        kk_[i] = kk; cc_[i] = c;
    }
    const uint32_t boff = (((uint32_t)(lid & 15)) * BNPH + ((lid >> 4) & 1) * 8) * 2 + wn * 2;

    auto load_stage = [&](int s, int kc) {
        const int k0 = kc * BK;
        uint32_t abase = sb + 1024 + s * ST_BYTES;
        uint32_t bbase = abase + A_ST;
        #pragma unroll
        for (int i = 0; i < 4; i++) {
            int idx = i * 256 + tid; int r = idx >> 2, c4 = idx & 3;
            cp_async16(abase + r * (BKPH * 2) + c4 * 16,
                       Ab + (size_t)r * HP2 + k0 + 8 * c4, 16u);   // k<=703 < HP2, pad zeros
        }
        #pragma unroll
        for (int i = 0; i < 2; i++) {
            int kq = k0 + kk_[i];
            bool v = (kq < H_DIM);
            cp_async16(bbase + (kk_[i] * BNPH + 8 * cc_[i]) * 2,
                       v ? (bptr[i] + (size_t)k0 * D_DIM) : (const __half*)g_Wdh,
                       v ? 16u : 0u);
        }
    };

    float acc[4][8][4];
    #pragma unroll
    for (int mi = 0; mi < 4; mi++)
        #pragma unroll
        for (int j = 0; j < 8; j++)
            #pragma unroll
            for (int cc = 0; cc < 4; cc++) acc[mi][j][cc] = 0.f;

    const int NK = (H_DIM + BK - 1) / BK;   // 22 (last stage: k 672..687 valid, rest zero)
    for (int s = 0; s < PRELOAD; s++) {
        if (s < NK) load_stage(s, s);
        cp_commit();
    }

    #pragma unroll 1
    for (int kc = 0; kc < NK; kc++) {
        cp_wait4();
        __syncthreads();
        if (kc + PRELOAD < NK) load_stage((kc + PRELOAD) % STAGES, kc + PRELOAD);
        cp_commit();
        const uint32_t* Asu = (const uint32_t*)(smem + 1024 + (kc % STAGES) * ST_BYTES);
        uint32_t baddr = sb + 1024 + (kc % STAGES) * ST_BYTES + A_ST + boff;
        gemm_stage(Asu, baddr, wm, g, t, acc);
    }

    #pragma unroll
    for (int mi = 0; mi < 4; mi++) {
        size_t r = (size_t)(e * CAP + m0 + wm + mi * 16 + g);
        #pragma unroll
        for (int j = 0; j < 8; j++) {
            int nc = d0 + wn + j * 8 + 2 * t;
            float* cc = acc[mi][j];
            *(float2*)(g_yb + r * D_DIM + nc)       = make_float2(cc[0], cc[1]);
            *(float2*)(g_yb + (r + 8) * D_DIM + nc) = make_float2(cc[2], cc[3]);
        }
    }
}

// ================= combine: y[t] = w0*yb[slot0] + w1*yb[slot1] =================
__global__ void combine_kernel(const float* __restrict__ scores, float* __restrict__ y) {
    const int t = blockIdx.x;
    int s0 = g_tok_slot[2 * t], s1 = g_tok_slot[2 * t + 1];
    float w0 = scores[2 * t], w1 = scores[2 * t + 1];
    if (s0 < 0) { w0 = 0.f; s0 = 0; }
    if (s1 < 0) { w1 = 0.f; s1 = 0; }
    const float4* r0 = (const float4*)g_yb + (size_t)s0 * (D_DIM / 4);
    const float4* r1 = (const float4*)g_yb + (size_t)s1 * (D_DIM / 4);
    float4* yo = (float4*)y + (size_t)t * (D_DIM / 4);
    #pragma unroll
    for (int j = 0; j < 2; j++) {
        int i = j * 256 + threadIdx.x;
        float4 a = r0[i], b = r1[i];
        float4 o;
        o.x = w0 * a.x + w1 * b.x;
        o.y = w0 * a.y + w1 * b.y;
        o.z = w0 * a.z + w1 * b.z;
        o.w = w0 * a.w + w1 * b.w;
        yo[i] = o;
    }
}

// ================= host =================
extern "C" void kernel_launch(void* const* d_in, const int* in_sizes, int n_in,
                              void* d_out, int out_size) {
    (void)in_sizes; (void)n_in; (void)out_size;
    const float* x           = (const float*)d_in[0];
    const int*   topk_idx    = (const int*)d_in[1];
    const float* topk_scores = (const float*)d_in[2];
    const float* W_gate      = (const float*)d_in[3];
    const float* W_up        = (const float*)d_in[4];
    const float* W_down      = (const float*)d_in[5];
    float* y = (float*)d_out;

    cudaFuncSetAttribute(gemm1_kernel, cudaFuncAttributeMaxDynamicSharedMemorySize, GEMM_SMEM);
    cudaFuncSetAttribute(gemm2_kernel, cudaFuncAttributeMaxDynamicSharedMemorySize, GEMM_SMEM);

    void *dWg, *dWu, *dWd, *dXr;
    cudaGetSymbolAddress(&dWg, g_Wgh);
    cudaGetSymbolAddress(&dWu, g_Wuh);
    cudaGetSymbolAddress(&dWd, g_Wdh);
    cudaGetSymbolAddress(&dXr, g_xh);

    const int W4 = (E_NUM * D_DIM * H_DIM) / 4;   // 2,818,048 (even)
    const int X4 = (T_TOK * D_DIM) / 4;           // 2,097,152 (even)

    zero_counts_kernel<<<1, 32>>>();
    dispatch_kernel<<<(T_TOK * 2 + 255) / 256, 256>>>(topk_idx);
    f2h_kernel<<<W4 / 512, 256>>>((const float4*)W_gate, (uint2*)dWg, W4 / 2);
    f2h_kernel<<<W4 / 512, 256>>>((const float4*)W_up,   (uint2*)dWu, W4 / 2);
    f2h_kernel<<<W4 / 512, 256>>>((const float4*)W_down, (uint2*)dWd, W4 / 2);
    f2h_kernel<<<X4 / 512, 256>>>((const float4*)x,      (uint2*)dXr, X4 / 2);
    gemm1_kernel<<<dim3(HP2 / 64, CAP / CTA_M, E_NUM), 256, GEMM_SMEM>>>();
    gemm2_kernel<<<dim3(D_DIM / CTA_N, CAP / CTA_M, E_NUM), 256, GEMM_SMEM>>>();
    combine_kernel<<<T_TOK, 256>>>(topk_scores, y);
}

// round 16
// speedup vs baseline: 1.0611x; 1.0611x over previous
#include <cuda_runtime.h>
#include <cuda_fp16.h>
#include <cstdint>
#include <math.h>

// ---------------- problem constants ----------------
#define T_TOK 4096
#define D_DIM 2048
#define H_DIM 688
#define HP2   704          // g_h pitch (pad cols exact zeros)
#define E_NUM 8
#define CAP   1536
#define NROWS (E_NUM * CAP)   // 12288

// GEMM tiling: CTA 128x128, 256 threads, 8 warps of 32x64 (4 in M, 2 in N), occupancy 2
#define CTA_M 128
#define CTA_N 128
#define BK 32                  // k-depth per stage = two mma-k
#define BKPH 40                // A smem pitch (halfs) = 20 u32: (g*20+t)%32 bijective
#define BNPH 136               // B smem pitch (halfs); 272B rows -> ldmatrix conflict-free
#define A_ST (CTA_M * BKPH * 2)   // 10240
#define B_ST (BK * BNPH * 2)      // 8704
#define ST_BYTES (A_ST + B_ST)    // 18944
#define STAGES 4
#define PRELOAD 3                 // wait_group 2
#define GEMM_SMEM (1024 + STAGES * ST_BYTES)   // 76800 -> 2 CTAs/SM

// ---------------- device scratch (static, no runtime allocs) ----------------
__device__ __align__(256) __half g_Wgh[(size_t)E_NUM * D_DIM * H_DIM];
__device__ __align__(256) __half g_Wuh[(size_t)E_NUM * D_DIM * H_DIM];
__device__ __align__(256) __half g_Wdh[(size_t)E_NUM * H_DIM * D_DIM];
__device__ __align__(256) __half g_xh [(size_t)T_TOK * D_DIM];
__device__ __align__(256) __half g_hh [(size_t)NROWS * HP2];
__device__ float g_yb [(size_t)NROWS * D_DIM];
__device__ int   g_row_token[NROWS];
__device__ int   g_tok_slot[T_TOK * 2];
__device__ int   g_counts[E_NUM];

// ---------------- helpers ----------------
__device__ __forceinline__ uint32_t smem_u32(const void* p) {
    uint32_t a;
    asm("{ .reg .u64 t; cvta.to.shared.u64 t, %1; cvt.u32.u64 %0, t; }" : "=r"(a) : "l"(p));
    return a;
}
__device__ __forceinline__ void cp_async16(uint32_t dst, const void* src, uint32_t sz) {
    asm volatile("cp.async.cg.shared.global [%0], [%1], 16, %2;" :: "r"(dst), "l"(src), "r"(sz) : "memory");
}
__device__ __forceinline__ void cp_commit() {
    asm volatile("cp.async.commit_group;" ::: "memory");
}
__device__ __forceinline__ void cp_wait2() {
    asm volatile("cp.async.wait_group 2;" ::: "memory");
}
// fp16 m16n8k16 row.col, fp32 accum: D += A*B
__device__ __forceinline__ void mma_f16(float* c, const uint32_t* a, const uint32_t* b) {
    asm volatile(
        "mma.sync.aligned.m16n8k16.row.col.f32.f16.f16.f32 "
        "{%0,%1,%2,%3}, {%4,%5,%6,%7}, {%8,%9}, {%0,%1,%2,%3};"
        : "+f"(c[0]), "+f"(c[1]), "+f"(c[2]), "+f"(c[3])
        : "r"(a[0]), "r"(a[1]), "r"(a[2]), "r"(a[3]), "r"(b[0]), "r"(b[1]));
}
__device__ __forceinline__ void ldsm_x4_trans(uint32_t& r0, uint32_t& r1, uint32_t& r2, uint32_t& r3,
                                              uint32_t addr) {
    asm volatile("ldmatrix.sync.aligned.m8n8.x4.trans.shared.b16 {%0,%1,%2,%3}, [%4];"
        : "=r"(r0), "=r"(r1), "=r"(r2), "=r"(r3) : "r"(addr));
}

// ================= prep: fp32 -> fp16 RN copies (MLP=2) =================
__global__ void f2h_kernel(const float4* __restrict__ src, uint2* __restrict__ dst, int half_n) {
    int i = blockIdx.x * 256 + threadIdx.x;
    float4 v0 = src[i];
    float4 v1 = src[i + half_n];
    __half2 a0 = __floats2half2_rn(v0.x, v0.y);
    __half2 b0 = __floats2half2_rn(v0.z, v0.w);
    __half2 a1 = __floats2half2_rn(v1.x, v1.y);
    __half2 b1 = __floats2half2_rn(v1.z, v1.w);
    uint2 o0, o1;
    o0.x = *reinterpret_cast<uint32_t*>(&a0);
    o0.y = *reinterpret_cast<uint32_t*>(&b0);
    o1.x = *reinterpret_cast<uint32_t*>(&a1);
    o1.y = *reinterpret_cast<uint32_t*>(&b1);
    dst[i] = o0;
    dst[i + half_n] = o1;
}

// ================= dispatch =================
__global__ void zero_counts_kernel() {
    if (threadIdx.x < E_NUM) g_counts[threadIdx.x] = 0;
}
__global__ void dispatch_kernel(const int* __restrict__ topk_idx) {
    int i = blockIdx.x * 256 + threadIdx.x;
    if (i >= T_TOK * 2) return;
    int e = topk_idx[i];
    int pos = atomicAdd(&g_counts[e], 1);
    if (pos < CAP) {
        int slot = e * CAP + pos;
        g_row_token[slot] = i >> 1;
        g_tok_slot[i] = slot;
    } else {
        g_tok_slot[i] = -1;
    }
}

// ================= GEMM inner stage (fp16, BK=32: two mma-k) =================
// 8 warps: wm=(w&3)*32, wn=(w>>2)*64; warp tile 32x64, acc[2][8][4].
__device__ __forceinline__ void gemm_stage(
    const uint32_t* __restrict__ Asu, uint32_t baddr,
    int wm, int g, int t, float acc[2][8][4])
{
    #pragma unroll
    for (int ks = 0; ks < 2; ks++) {
        uint32_t af[2][4];
        #pragma unroll
        for (int mi = 0; mi < 2; mi++) {
            int rb = (wm + mi * 16 + g) * (BKPH / 2) + ks * 8 + t;   // u32 units: 20/row
            af[mi][0] = Asu[rb];
            af[mi][1] = Asu[rb + 8 * (BKPH / 2)];
            af[mi][2] = Asu[rb + 4];
            af[mi][3] = Asu[rb + 8 * (BKPH / 2) + 4];
        }
        uint32_t bf[8][2];
        uint32_t bks = baddr + ks * (16 * BNPH * 2);
        #pragma unroll
        for (int q = 0; q < 4; q++)
            ldsm_x4_trans(bf[2 * q][0], bf[2 * q][1], bf[2 * q + 1][0], bf[2 * q + 1][1],
                          bks + q * 32);
        #pragma unroll
        for (int mi = 0; mi < 2; mi++)
            #pragma unroll
            for (int j = 0; j < 8; j++)
                mma_f16(acc[mi][j], af[mi], bf[j]);
    }
}

// ================= GEMM1: h = silu(x*Wg) * (x*Wu) =================
// grid (11, 12, 8) = (64-h tile, 128-m tile, expert), 256 threads.
// B cols interleave gate/up per 8: chunk c: sel=c&1, h_rel=8*(c>>1), n0=8c.
__global__ void __launch_bounds__(256, 2) gemm1_kernel() {
    extern __shared__ char smem[];
    const int e = blockIdx.z, mt = blockIdx.y;
    int count = g_counts[e]; if (count > CAP) count = CAP;
    const int m0 = mt * CTA_M;
    if (m0 >= count) return;
    const int h0 = blockIdx.x * 64;
    const uint32_t sb = smem_u32(smem);
    const int tid = threadIdx.x, w = tid >> 5, lid = tid & 31;
    const int wm = (w & 3) * 32, wn = (w >> 2) * 64;
    const int g = lid >> 2, t = lid & 3;
    int* tok_sm = (int*)smem;

    if (tid < CTA_M) {
        int m = m0 + tid;
        tok_sm[tid] = (m < count) ? g_row_token[e * CAP + m] : -1;
    }
    __syncthreads();

    // B chunk geometry: 2 chunks/thread over 512 chunks of [32][128]
    const __half* wsrc[2];
    uint32_t bsz_[2]; int kk_[2]; int bn_[2];
    #pragma unroll
    for (int i = 0; i < 2; i++) {
        int chunk = i * 256 + tid;
        int kk = chunk >> 4;            // 0..31
        int c  = chunk & 15;
        int sel = c & 1;
        int hrel = 8 * (c >> 1);
        int h_glob = h0 + hrel;
        bsz_[i] = (h_glob < H_DIM) ? 16u : 0u;
        int h_src = (h_glob < H_DIM) ? h_glob : 0;
        wsrc[i] = (sel ? g_Wuh : g_Wgh) + ((size_t)e * D_DIM + kk) * H_DIM + h_src;
        kk_[i] = kk; bn_[i] = 8 * c;
    }

    const uint32_t boff = (((uint32_t)(lid & 15)) * BNPH + ((lid >> 4) & 1) * 8) * 2 + wn * 2;

    auto load_stage = [&](int s, int kc) {
        const int k0 = kc * BK;
        uint32_t abase = sb + 1024 + s * ST_BYTES;
        uint32_t bbase = abase + A_ST;
        #pragma unroll
        for (int i = 0; i < 2; i++) {
            int idx = i * 256 + tid; int r = idx >> 2, c4 = idx & 3;
            int tok = tok_sm[r];
            const __half* src = (tok >= 0) ? (g_xh + (size_t)tok * D_DIM + k0 + 8 * c4) : g_xh;
            cp_async16(abase + r * (BKPH * 2) + c4 * 16, src, (tok >= 0) ? 16u : 0u);
        }
        #pragma unroll
        for (int i = 0; i < 2; i++)
            cp_async16(bbase + (kk_[i] * BNPH + bn_[i]) * 2,
                       wsrc[i] + (size_t)k0 * H_DIM, bsz_[i]);
    };

    float acc[2][8][4];
    #pragma unroll
    for (int mi = 0; mi < 2; mi++)
        #pragma unroll
        for (int j = 0; j < 8; j++)
            #pragma unroll
            for (int cc = 0; cc < 4; cc++) acc[mi][j][cc] = 0.f;

    const int NK = D_DIM / BK;   // 64
    for (int s = 0; s < PRELOAD; s++) {
        if (s < NK) load_stage(s, s);
        cp_commit();
    }

    #pragma unroll 1
    for (int kc = 0; kc < NK; kc++) {
        cp_wait2();
        __syncthreads();
        if (kc + PRELOAD < NK) load_stage((kc + PRELOAD) & 3, kc + PRELOAD);
        cp_commit();
        const uint32_t* Asu = (const uint32_t*)(smem + 1024 + (kc & 3) * ST_BYTES);
        uint32_t baddr = sb + 1024 + (kc & 3) * ST_BYTES + A_ST + boff;
        gemm_stage(Asu, baddr, wm, g, t, acc);
    }

    // epilogue: silu(gate)*up -> g_hh (fp16). ntile pairs (2p, 2p+1); h = h0 + wn/2 + 8p + 2t.
    #pragma unroll
    for (int mi = 0; mi < 2; mi++) {
        size_t r = (size_t)(e * CAP + m0 + wm + mi * 16 + g);
        #pragma unroll
        for (int p = 0; p < 4; p++) {
            float* ga = acc[mi][2 * p];
            float* ua = acc[mi][2 * p + 1];
            int hc = h0 + (wn >> 1) + 8 * p + 2 * t;
            float h00 = ga[0] / (1.f + __expf(-ga[0])) * ua[0];
            float h01 = ga[1] / (1.f + __expf(-ga[1])) * ua[1];
            float h10 = ga[2] / (1.f + __expf(-ga[2])) * ua[2];
            float h11 = ga[3] / (1.f + __expf(-ga[3])) * ua[3];
            *(__half2*)(g_hh + r * HP2 + hc)       = __floats2half2_rn(h00, h01);
            *(__half2*)(g_hh + (r + 8) * HP2 + hc) = __floats2half2_rn(h10, h11);
        }
    }
}

// ================= GEMM2: yb = h * W_down (K=688, 22 stages, tail zero-filled) =================
// grid (16, 12, 8) = (128-d tile, 128-m tile, expert), 256 threads.
__global__ void __launch_bounds__(256, 2) gemm2_kernel() {
    extern __shared__ char smem[];
    const int e = blockIdx.z, mt = blockIdx.y;
    int count = g_counts[e]; if (count > CAP) count = CAP;
    const int m0 = mt * CTA_M;
    if (m0 >= count) return;
    const int d0 = blockIdx.x * CTA_N;
    const uint32_t sb = smem_u32(smem);
    const int tid = threadIdx.x, w = tid >> 5, lid = tid & 31;
    const int wm = (w & 3) * 32, wn = (w >> 2) * 64;
    const int g = lid >> 2, t = lid & 3;

    const __half* Ab = g_hh + (size_t)(e * CAP + m0) * HP2;
    const __half* bptr[2]; int kk_[2]; int cc_[2];
    #pragma unroll
    for (int i = 0; i < 2; i++) {
        int chunk = i * 256 + tid;
        int kk = chunk >> 4, c = chunk & 15;
        bptr[i] = g_Wdh + ((size_t)e * H_DIM + kk) * D_DIM + d0 + 8 * c;
        kk_[i] = kk; cc_[i] = c;
    }
    const uint32_t boff = (((uint32_t)(lid & 15)) * BNPH + ((lid >> 4) & 1) * 8) * 2 + wn * 2;

    auto load_stage = [&](int s, int kc) {
        const int k0 = kc * BK;
        uint32_t abase = sb + 1024 + s * ST_BYTES;
        uint32_t bbase = abase + A_ST;
        #pragma unroll
        for (int i = 0; i < 2; i++) {
            int idx = i * 256 + tid; int r = idx >> 2, c4 = idx & 3;
            cp_async16(abase + r * (BKPH * 2) + c4 * 16,
                       Ab + (size_t)r * HP2 + k0 + 8 * c4, 16u);   // k<=703 < HP2, pad zeros
        }
        #pragma unroll
        for (int i = 0; i < 2; i++) {
            int kq = k0 + kk_[i];
            bool v = (kq < H_DIM);
            cp_async16(bbase + (kk_[i] * BNPH + 8 * cc_[i]) * 2,
                       v ? (bptr[i] + (size_t)k0 * D_DIM) : (const __half*)g_Wdh,
                       v ? 16u : 0u);
        }
    };

    float acc[2][8][4];
    #pragma unroll
    for (int mi = 0; mi < 2; mi++)
        #pragma unroll
        for (int j = 0; j < 8; j++)
            #pragma unroll
            for (int cc = 0; cc < 4; cc++) acc[mi][j][cc] = 0.f;

    const int NK = (H_DIM + BK - 1) / BK;   // 22 (last stage: k 672..687 valid, rest zero)
    for (int s = 0; s < PRELOAD; s++) {
        if (s < NK) load_stage(s, s);
        cp_commit();
    }

    #pragma unroll 1
    for (int kc = 0; kc < NK; kc++) {
        cp_wait2();
        __syncthreads();
        if (kc + PRELOAD < NK) load_stage((kc + PRELOAD) & 3, kc + PRELOAD);
        cp_commit();
        const uint32_t* Asu = (const uint32_t*)(smem + 1024 + (kc & 3) * ST_BYTES);
        uint32_t baddr = sb + 1024 + (kc & 3) * ST_BYTES + A_ST + boff;
        gemm_stage(Asu, baddr, wm, g, t, acc);
    }

    #pragma unroll
    for (int mi = 0; mi < 2; mi++) {
        size_t r = (size_t)(e * CAP + m0 + wm + mi * 16 + g);
        #pragma unroll
        for (int j = 0; j < 8; j++) {
            int nc = d0 + wn + j * 8 + 2 * t;
            float* cc = acc[mi][j];
            *(float2*)(g_yb + r * D_DIM + nc)       = make_float2(cc[0], cc[1]);
            *(float2*)(g_yb + (r + 8) * D_DIM + nc) = make_float2(cc[2], cc[3]);
        }
    }
}

// ================= combine: y[t] = w0*yb[slot0] + w1*yb[slot1] =================
__global__ void combine_kernel(const float* __restrict__ scores, float* __restrict__ y) {
    const int t = blockIdx.x;
    int s0 = g_tok_slot[2 * t], s1 = g_tok_slot[2 * t + 1];
    float w0 = scores[2 * t], w1 = scores[2 * t + 1];
    if (s0 < 0) { w0 = 0.f; s0 = 0; }
    if (s1 < 0) { w1 = 0.f; s1 = 0; }
    const float4* r0 = (const float4*)g_yb + (size_t)s0 * (D_DIM / 4);
    const float4* r1 = (const float4*)g_yb + (size_t)s1 * (D_DIM / 4);
    float4* yo = (float4*)y + (size_t)t * (D_DIM / 4);
    #pragma unroll
    for (int j = 0; j < 2; j++) {
        int i = j * 256 + threadIdx.x;
        float4 a = r0[i], b = r1[i];
        float4 o;
        o.x = w0 * a.x + w1 * b.x;
        o.y = w0 * a.y + w1 * b.y;
        o.z = w0 * a.z + w1 * b.z;
        o.w = w0 * a.w + w1 * b.w;
        yo[i] = o;
    }
}

// ================= host =================
extern "C" void kernel_launch(void* const* d_in, const int* in_sizes, int n_in,
                              void* d_out, int out_size) {
    (void)in_sizes; (void)n_in; (void)out_size;
    const float* x           = (const float*)d_in[0];
    const int*   topk_idx    = (const int*)d_in[1];
    const float* topk_scores = (const float*)d_in[2];
    const float* W_gate      = (const float*)d_in[3];
    const float* W_up        = (const float*)d_in[4];
    const float* W_down      = (const float*)d_in[5];
    float* y = (float*)d_out;

    cudaFuncSetAttribute(gemm1_kernel, cudaFuncAttributeMaxDynamicSharedMemorySize, GEMM_SMEM);
    cudaFuncSetAttribute(gemm2_kernel, cudaFuncAttributeMaxDynamicSharedMemorySize, GEMM_SMEM);

    void *dWg, *dWu, *dWd, *dXr;
    cudaGetSymbolAddress(&dWg, g_Wgh);
    cudaGetSymbolAddress(&dWu, g_Wuh);
    cudaGetSymbolAddress(&dWd, g_Wdh);
    cudaGetSymbolAddress(&dXr, g_xh);

    const int W4 = (E_NUM * D_DIM * H_DIM) / 4;   // 2,818,048 (even)
    const int X4 = (T_TOK * D_DIM) / 4;           // 2,097,152 (even)

    zero_counts_kernel<<<1, 32>>>();
    dispatch_kernel<<<(T_TOK * 2 + 255) / 256, 256>>>(topk_idx);
    f2h_kernel<<<W4 / 512, 256>>>((const float4*)W_gate, (uint2*)dWg, W4 / 2);
    f2h_kernel<<<W4 / 512, 256>>>((const float4*)W_up,   (uint2*)dWu, W4 / 2);
    f2h_kernel<<<W4 / 512, 256>>>((const float4*)W_down, (uint2*)dWd, W4 / 2);
    f2h_kernel<<<X4 / 512, 256>>>((const float4*)x,      (uint2*)dXr, X4 / 2);
    gemm1_kernel<<<dim3(HP2 / 64, CAP / CTA_M, E_NUM), 256, GEMM_SMEM>>>();
    gemm2_kernel<<<dim3(D_DIM / CTA_N, CAP / CTA_M, E_NUM), 256, GEMM_SMEM>>>();
    combine_kernel<<<T_TOK, 256>>>(topk_scores, y);
}